// round 13
// baseline (speedup 1.0000x reference)
#include <cuda_runtime.h>
#include <cstdint>

#define SEQ  4096
#define HID  1024
#define NCLS 256

typedef unsigned long long ull;

// ---------------- scratch (device globals) ----------------
__device__ float g_table[NCLS * 4 * HID];   //  4 MB  layer0 pre-activation table
__device__ float g_pre1 [SEQ  * 4 * HID];   // 64 MB  layer1 pre
__device__ float g_hs0  [SEQ * HID];        // 16 MB  h0 (GEMM input)
__device__ float g_hs1  [SEQ * HID];        // 16 MB  h1 (finals)
__device__ ull   g_tg0  [SEQ * HID];        // 32 MB  tagged h0 handoff
__device__ ull   g_tg1  [SEQ * HID];        // 32 MB  tagged h1 handoff
__device__ ull   g_tg2  [SEQ * NCLS];       //  8 MB  tagged h2 handoff
__device__ float g_cfin [2 * HID + NCLS];   // c0, c1, c2 finals
__device__ unsigned int g_gen;

// ---------------- helpers (R3-original) ----------------
__device__ __forceinline__ float fsig(float x) {
    return __fdividef(1.0f, 1.0f + __expf(-x));
}
__device__ __forceinline__ float ftanh(float x) {
    float a = fabsf(x);
    float e = __expf(2.0f * a);
    float r = 1.0f - __fdividef(2.0f, e + 1.0f);   // (e-1)/(e+1), overflow-safe
    return copysignf(r, x);
}
__device__ __forceinline__ ull ld_tag(const ull* p) {
    ull v;
    asm volatile("ld.relaxed.gpu.global.b64 %0, [%1];" : "=l"(v) : "l"(p) : "memory");
    return v;
}
__device__ __forceinline__ void st_tag(ull* p, ull v) {
    asm volatile("st.relaxed.gpu.global.b64 [%0], %1;" :: "l"(p), "l"(v) : "memory");
}
__device__ __forceinline__ ull fma2(ull a, ull b, ull c) {
    ull d;
    asm("fma.rn.f32x2 %0, %1, %2, %3;" : "=l"(d) : "l"(a), "l"(b), "l"(c));
    return d;
}
__device__ __forceinline__ ull add2(ull a, ull b) {
    ull d;
    asm("add.rn.f32x2 %0, %1, %2;" : "=l"(d) : "l"(a), "l"(b));
    return d;
}
__device__ __forceinline__ ull pack2(float lo, float hi) {
    ull d;
    asm("mov.b64 %0, {%1, %2};" : "=l"(d) : "f"(lo), "f"(hi));
    return d;
}
__device__ __forceinline__ float lo32(ull v) { return __uint_as_float((unsigned)v); }
__device__ __forceinline__ float hi32(ull v) { return __uint_as_float((unsigned)(v >> 32)); }

__global__ void bump_gen_kernel() { if (threadIdx.x == 0) g_gen += 1u; }

// ---------------- GEMM (R3-original):  C = A @ B^T + b1 + b2 ----------------
template<int WHICH>
__global__ void __launch_bounds__(256)
gemm_bias(const float* __restrict__ Ain, const float* __restrict__ B,
          const float* __restrict__ b1, const float* __restrict__ b2,
          int M, int N, int K)
{
    const float* A = (WHICH == 1) ? g_hs0 : Ain;
    float*       C = (WHICH == 0) ? g_table : g_pre1;

    __shared__ float As[16][136];
    __shared__ float Bs[16][72];

    const int m0 = blockIdx.y * 128;
    const int n0 = blockIdx.x * 64;
    const int tid = threadIdx.x;
    const int tm = tid >> 4;
    const int tn = tid & 15;
    const int lra = tid >> 1;
    const int lka = (tid & 1) * 8;
    const int lrb = tid >> 2;
    const int lkb = (tid & 3) * 4;

    float acc[8][4];
#pragma unroll
    for (int i = 0; i < 8; i++)
#pragma unroll
        for (int j = 0; j < 4; j++) acc[i][j] = 0.0f;

    for (int kt = 0; kt < K; kt += 16) {
        float4 a0 = *reinterpret_cast<const float4*>(&A[(size_t)(m0 + lra) * K + kt + lka]);
        float4 a1 = *reinterpret_cast<const float4*>(&A[(size_t)(m0 + lra) * K + kt + lka + 4]);
        float4 bv = *reinterpret_cast<const float4*>(&B[(size_t)(n0 + lrb) * K + kt + lkb]);
        __syncthreads();
        As[lka + 0][lra] = a0.x; As[lka + 1][lra] = a0.y; As[lka + 2][lra] = a0.z; As[lka + 3][lra] = a0.w;
        As[lka + 4][lra] = a1.x; As[lka + 5][lra] = a1.y; As[lka + 6][lra] = a1.z; As[lka + 7][lra] = a1.w;
        Bs[lkb + 0][lrb] = bv.x; Bs[lkb + 1][lrb] = bv.y; Bs[lkb + 2][lrb] = bv.z; Bs[lkb + 3][lrb] = bv.w;
        __syncthreads();
#pragma unroll
        for (int kk = 0; kk < 16; kk++) {
            float4 a4 = *reinterpret_cast<const float4*>(&As[kk][tm * 8]);
            float4 a5 = *reinterpret_cast<const float4*>(&As[kk][tm * 8 + 4]);
            float4 b4 = *reinterpret_cast<const float4*>(&Bs[kk][tn * 4]);
            float a[8] = {a4.x, a4.y, a4.z, a4.w, a5.x, a5.y, a5.z, a5.w};
            float b[4] = {b4.x, b4.y, b4.z, b4.w};
#pragma unroll
            for (int i = 0; i < 8; i++)
#pragma unroll
                for (int j = 0; j < 4; j++) acc[i][j] += a[i] * b[j];
        }
    }

    const int col0 = n0 + tn * 4;
    float4 v1 = *reinterpret_cast<const float4*>(&b1[col0]);
    float4 v2 = *reinterpret_cast<const float4*>(&b2[col0]);
    float bias[4] = {v1.x + v2.x, v1.y + v2.y, v1.z + v2.z, v1.w + v2.w};
#pragma unroll
    for (int i = 0; i < 8; i++) {
        int row = m0 + tm * 8 + i;
        float4 o;
        o.x = acc[i][0] + bias[0];
        o.y = acc[i][1] + bias[1];
        o.z = acc[i][2] + bias[2];
        o.w = acc[i][3] + bias[3];
        *reinterpret_cast<float4*>(&C[(size_t)row * N + col0]) = o;
    }
}

// ---------------- layer-0 scan (R11 bytes: R3 + backoff) ----------------
__global__ void __launch_bounds__(256, 1)
lstm_scan0(const float* __restrict__ whh, const int* __restrict__ tokens)
{
    const int tid = threadIdx.x;
    const int w = tid >> 5;
    const int l = tid & 31;
    const int out = blockIdx.x * 8 + w;
    const unsigned tb = g_gen * (unsigned)(SEQ + 1);

    __shared__ __align__(16) float sh[2][HID];
    __shared__ int stok[SEQ];

    ulonglong2 wq[4][8];
#pragma unroll
    for (int r = 0; r < 4; r++)
#pragma unroll
        for (int i = 0; i < 8; i++)
            wq[r][i] = *reinterpret_cast<const ulonglong2*>(
                whh + (size_t)(r * HID + out) * HID + i * 128 + 4 * l);

    for (int i = tid; i < SEQ; i += 256) stok[i] = tokens[i];
    for (int i = tid; i < HID; i += 256) sh[0][i] = 0.0f;
    __syncthreads();

    auto loadpre = [&](int tt, int r) -> float {
        return __ldg(&g_table[(size_t)stok[tt] * (4 * HID) + r * HID + out]);
    };

    float c = 0.0f;
    float pv = (l < 4) ? loadpre(0, l) : 0.0f;

    for (int t = 0; t < SEQ; t++) {
        float pvn = (l < 4 && t + 1 < SEQ) ? loadpre(t + 1, l) : 0.0f;

        float* shb = sh[t & 1];
        if (t > 0) {
            const ull* src = g_tg0 + (size_t)(t - 1) * HID;
            const unsigned expect = tb + (unsigned)t;
            ull v[4];
#pragma unroll
            for (int j = 0; j < 4; j++) v[j] = ld_tag(src + tid + 256 * j);
            while (true) {
                bool ok = true;
#pragma unroll
                for (int j = 0; j < 4; j++) ok &= ((unsigned)(v[j] >> 32) == expect);
                if (ok) break;
                __nanosleep(64);
#pragma unroll
                for (int j = 0; j < 4; j++) v[j] = ld_tag(src + tid + 256 * j);
            }
#pragma unroll
            for (int j = 0; j < 4; j++)
                shb[tid + 256 * j] = __uint_as_float((unsigned)v[j]);
        }
        __syncthreads();

        ull acc[4] = {0ull, 0ull, 0ull, 0ull};
#pragma unroll
        for (int i = 0; i < 8; i++) {
            ulonglong2 hv = *reinterpret_cast<const ulonglong2*>(shb + i * 128 + 4 * l);
#pragma unroll
            for (int r = 0; r < 4; r++) {
                acc[r] = fma2(wq[r][i].x, hv.x, acc[r]);
                acc[r] = fma2(wq[r][i].y, hv.y, acc[r]);
            }
        }
        float g[4];
#pragma unroll
        for (int r = 0; r < 4; r++) g[r] = lo32(acc[r]) + hi32(acc[r]);
#pragma unroll
        for (int s = 16; s > 0; s >>= 1)
#pragma unroll
            for (int r = 0; r < 4; r++) g[r] += __shfl_xor_sync(0xffffffffu, g[r], s);

        const float p0 = __shfl_sync(0xffffffffu, pv, 0);
        const float p1 = __shfl_sync(0xffffffffu, pv, 1);
        const float p2 = __shfl_sync(0xffffffffu, pv, 2);
        const float p3 = __shfl_sync(0xffffffffu, pv, 3);

        c = fsig(g[1] + p1) * c + fsig(g[0] + p0) * ftanh(g[2] + p2);
        const float h = fsig(g[3] + p3) * ftanh(c);

        if (l == 0) {
            st_tag(g_tg0 + (size_t)t * HID + out,
                   ((ull)(tb + (unsigned)t + 1u) << 32) | (ull)__float_as_uint(h));
            g_hs0[(size_t)t * HID + out] = h;
            if (t == SEQ - 1) g_cfin[out] = c;
        }
        pv = pvn;
    }
}

// ---------------- mega kernel: layer1 (128 CTAs) + layer2 (16 CTAs) --------
// blockIdx 0..127: layer1 scan, R11 bytes. blockIdx 128..143: layer2 on spare
// SMs, 16 outputs/CTA, polls g_tg1/g_tg2 with NANOSLEEP BACKOFF (the single
// change vs R10 — kills spin duty cycle that dragged the whole chip).
__global__ void __launch_bounds__(256, 1)
lstm_scan12(const float* __restrict__ whh1, const float* __restrict__ wih2,
            const float* __restrict__ whh2, const float* __restrict__ bih2,
            const float* __restrict__ bhh2, float* __restrict__ outp)
{
    const int tid = threadIdx.x;
    const int w = tid >> 5;
    const int l = tid & 31;
    const unsigned tb = g_gen * (unsigned)(SEQ + 1);

    if (blockIdx.x < 128) {
        // ===================== LAYER 1 (R11 bytes) =====================
        const int out = blockIdx.x * 8 + w;
        __shared__ __align__(16) float sh[2][HID];

        ulonglong2 wq[4][8];
#pragma unroll
        for (int r = 0; r < 4; r++)
#pragma unroll
            for (int i = 0; i < 8; i++)
                wq[r][i] = *reinterpret_cast<const ulonglong2*>(
                    whh1 + (size_t)(r * HID + out) * HID + i * 128 + 4 * l);

        for (int i = tid; i < HID; i += 256) sh[0][i] = 0.0f;
        __syncthreads();

        auto loadpre = [&](int tt, int r) -> float {
            return __ldg(&g_pre1[(size_t)tt * (4 * HID) + r * HID + out]);
        };

        float c = 0.0f;
        float pv = (l < 4) ? loadpre(0, l) : 0.0f;

        for (int t = 0; t < SEQ; t++) {
            float pvn = (l < 4 && t + 1 < SEQ) ? loadpre(t + 1, l) : 0.0f;

            float* shb = sh[t & 1];
            if (t > 0) {
                const ull* src = g_tg1 + (size_t)(t - 1) * HID;
                const unsigned expect = tb + (unsigned)t;
                ull v[4];
#pragma unroll
                for (int j = 0; j < 4; j++) v[j] = ld_tag(src + tid + 256 * j);
                while (true) {
                    bool ok = true;
#pragma unroll
                    for (int j = 0; j < 4; j++) ok &= ((unsigned)(v[j] >> 32) == expect);
                    if (ok) break;
                    __nanosleep(64);
#pragma unroll
                    for (int j = 0; j < 4; j++) v[j] = ld_tag(src + tid + 256 * j);
                }
#pragma unroll
                for (int j = 0; j < 4; j++)
                    shb[tid + 256 * j] = __uint_as_float((unsigned)v[j]);
            }
            __syncthreads();

            ull acc[4] = {0ull, 0ull, 0ull, 0ull};
#pragma unroll
            for (int i = 0; i < 8; i++) {
                ulonglong2 hv = *reinterpret_cast<const ulonglong2*>(shb + i * 128 + 4 * l);
#pragma unroll
                for (int r = 0; r < 4; r++) {
                    acc[r] = fma2(wq[r][i].x, hv.x, acc[r]);
                    acc[r] = fma2(wq[r][i].y, hv.y, acc[r]);
                }
            }
            float g[4];
#pragma unroll
            for (int r = 0; r < 4; r++) g[r] = lo32(acc[r]) + hi32(acc[r]);
#pragma unroll
            for (int s = 16; s > 0; s >>= 1)
#pragma unroll
                for (int r = 0; r < 4; r++) g[r] += __shfl_xor_sync(0xffffffffu, g[r], s);

            const float p0 = __shfl_sync(0xffffffffu, pv, 0);
            const float p1 = __shfl_sync(0xffffffffu, pv, 1);
            const float p2 = __shfl_sync(0xffffffffu, pv, 2);
            const float p3 = __shfl_sync(0xffffffffu, pv, 3);

            c = fsig(g[1] + p1) * c + fsig(g[0] + p0) * ftanh(g[2] + p2);
            const float h = fsig(g[3] + p3) * ftanh(c);

            if (l == 0) {
                st_tag(g_tg1 + (size_t)t * HID + out,
                       ((ull)(tb + (unsigned)t + 1u) << 32) | (ull)__float_as_uint(h));
                g_hs1[(size_t)t * HID + out] = h;
                if (t == SEQ - 1) g_cfin[HID + out] = c;
            }
            pv = pvn;
        }
    } else {
        // ============ LAYER 2 (16 spare-SM CTAs, backoff pollers) ==========
        const int cta2 = blockIdx.x - 128;         // 0..15
        const int oA = cta2 * 16 + 2 * w;          // warp owns outputs oA, oA+1
        const int oB = oA + 1;

        __shared__ __align__(16) float s1[2][HID];
        __shared__ __align__(16) float s2[2][NCLS];

        ulonglong2 whA[4][2], whB[4][2];
#pragma unroll
        for (int r = 0; r < 4; r++)
#pragma unroll
            for (int i = 0; i < 2; i++) {
                whA[r][i] = *reinterpret_cast<const ulonglong2*>(
                    whh2 + (size_t)(r * NCLS + oA) * NCLS + i * 128 + 4 * l);
                whB[r][i] = *reinterpret_cast<const ulonglong2*>(
                    whh2 + (size_t)(r * NCLS + oB) * NCLS + i * 128 + 4 * l);
            }
        float bA[4], bB[4];
#pragma unroll
        for (int r = 0; r < 4; r++) {
            bA[r] = __ldg(&bih2[r * NCLS + oA]) + __ldg(&bhh2[r * NCLS + oA]);
            bB[r] = __ldg(&bih2[r * NCLS + oB]) + __ldg(&bhh2[r * NCLS + oB]);
        }
        const float* wpA[4];
        const float* wpB[4];
#pragma unroll
        for (int r = 0; r < 4; r++) {
            wpA[r] = wih2 + (size_t)(r * NCLS + oA) * HID + 4 * l;
            wpB[r] = wih2 + (size_t)(r * NCLS + oB) * HID + 4 * l;
        }

        for (int i = tid; i < NCLS; i += 256) s2[0][i] = 0.0f;
        __syncthreads();

        float cA = 0.0f, cB = 0.0f;

        for (int t = 0; t < SEQ; t++) {
            float* p1 = s1[t & 1];
            float* p2 = s2[t & 1];
            {
                const ull* src1 = g_tg1 + (size_t)t * HID;
                const unsigned e1 = tb + (unsigned)t + 1u;   // h1_t
                const ull* src2 = g_tg2 + (size_t)(t - 1) * NCLS;
                const unsigned e2 = tb + (unsigned)t;        // h2_{t-1}
                ull v[4];
#pragma unroll
                for (int j = 0; j < 4; j++) v[j] = ld_tag(src1 + tid + 256 * j);
                ull u = 0;
                if (t > 0) u = ld_tag(src2 + tid);
                while (true) {
                    bool ok = true;
#pragma unroll
                    for (int j = 0; j < 4; j++) ok &= ((unsigned)(v[j] >> 32) == e1);
                    if (t > 0) ok &= ((unsigned)(u >> 32) == e2);
                    if (ok) break;
                    __nanosleep(256);   // THE fix: low-duty spin on spare SMs
#pragma unroll
                    for (int j = 0; j < 4; j++) v[j] = ld_tag(src1 + tid + 256 * j);
                    if (t > 0) u = ld_tag(src2 + tid);
                }
#pragma unroll
                for (int j = 0; j < 4; j++)
                    p1[tid + 256 * j] = __uint_as_float((unsigned)v[j]);
                if (t > 0) p2[tid] = __uint_as_float((unsigned)u);
            }
            __syncthreads();

            ull aA[4] = {0ull, 0ull, 0ull, 0ull};
            ull aB[4] = {0ull, 0ull, 0ull, 0ull};
#pragma unroll
            for (int i = 0; i < 8; i++) {
                ulonglong2 hv = *reinterpret_cast<const ulonglong2*>(p1 + i * 128 + 4 * l);
#pragma unroll
                for (int r = 0; r < 4; r++) {
                    ulonglong2 wa = *reinterpret_cast<const ulonglong2*>(wpA[r] + i * 128);
                    ulonglong2 wb = *reinterpret_cast<const ulonglong2*>(wpB[r] + i * 128);
                    aA[r] = fma2(wa.x, hv.x, aA[r]); aA[r] = fma2(wa.y, hv.y, aA[r]);
                    aB[r] = fma2(wb.x, hv.x, aB[r]); aB[r] = fma2(wb.y, hv.y, aB[r]);
                }
            }
#pragma unroll
            for (int i = 0; i < 2; i++) {
                ulonglong2 hv = *reinterpret_cast<const ulonglong2*>(p2 + i * 128 + 4 * l);
#pragma unroll
                for (int r = 0; r < 4; r++) {
                    aA[r] = fma2(whA[r][i].x, hv.x, aA[r]); aA[r] = fma2(whA[r][i].y, hv.y, aA[r]);
                    aB[r] = fma2(whB[r][i].x, hv.x, aB[r]); aB[r] = fma2(whB[r][i].y, hv.y, aB[r]);
                }
            }
            ull q0 = pack2(lo32(aA[0]) + hi32(aA[0]), lo32(aB[0]) + hi32(aB[0]));
            ull q1 = pack2(lo32(aA[1]) + hi32(aA[1]), lo32(aB[1]) + hi32(aB[1]));
            ull q2 = pack2(lo32(aA[2]) + hi32(aA[2]), lo32(aB[2]) + hi32(aB[2]));
            ull q3 = pack2(lo32(aA[3]) + hi32(aA[3]), lo32(aB[3]) + hi32(aB[3]));
#pragma unroll
            for (int s = 16; s > 0; s >>= 1) {
                q0 = add2(q0, __shfl_xor_sync(0xffffffffu, q0, s));
                q1 = add2(q1, __shfl_xor_sync(0xffffffffu, q1, s));
                q2 = add2(q2, __shfl_xor_sync(0xffffffffu, q2, s));
                q3 = add2(q3, __shfl_xor_sync(0xffffffffu, q3, s));
            }
            cA = fsig(lo32(q1) + bA[1]) * cA
               + fsig(lo32(q0) + bA[0]) * ftanh(lo32(q2) + bA[2]);
            const float hA = fsig(lo32(q3) + bA[3]) * ftanh(cA);
            cB = fsig(hi32(q1) + bB[1]) * cB
               + fsig(hi32(q0) + bB[0]) * ftanh(hi32(q2) + bB[2]);
            const float hB = fsig(hi32(q3) + bB[3]) * ftanh(cB);

            if (l == 0) {
                const ull tagv = (ull)(tb + (unsigned)t + 1u) << 32;
                st_tag(g_tg2 + (size_t)t * NCLS + oA, tagv | (ull)__float_as_uint(hA));
                st_tag(g_tg2 + (size_t)t * NCLS + oB, tagv | (ull)__float_as_uint(hB));
                outp[(size_t)t * NCLS + oA] = hA;
                outp[(size_t)t * NCLS + oB] = hB;
                if (t == SEQ - 1) {
                    g_cfin[2 * HID + oA] = cA;
                    g_cfin[2 * HID + oB] = cB;
                }
            }
        }
    }
}

// ---------------- final output assembly ----------------
__global__ void finalize_kernel(float* __restrict__ out) {
    int i = blockIdx.x * blockDim.x + threadIdx.x;
    const int OB = SEQ * NCLS;
    if (i < 1024)      out[OB + i] = g_hs0[(SEQ - 1) * HID + i];
    else if (i < 2048) out[OB + i] = g_hs1[(SEQ - 1) * HID + (i - 1024)];
    else if (i < 3072) out[OB + i] = g_cfin[i - 2048];                   // c0
    else if (i < 4096) out[OB + i] = g_cfin[HID + (i - 3072)];           // c1
    else if (i < 4352) out[OB + i] = out[(SEQ - 1) * NCLS + (i - 4096)]; // h2
    else if (i < 4608) out[OB + i] = g_cfin[2 * HID + (i - 4352)];       // c2
}

// ---------------- launch ----------------
extern "C" void kernel_launch(void* const* d_in, const int* in_sizes, int n_in,
                              void* d_out, int out_size)
{
    const int*   tokens = (const int*)  d_in[0];
    const float* embed  = (const float*)d_in[1];
    const float* w_ih0  = (const float*)d_in[2];
    const float* w_hh0  = (const float*)d_in[3];
    const float* b_ih0  = (const float*)d_in[4];
    const float* b_hh0  = (const float*)d_in[5];
    const float* w_ih1  = (const float*)d_in[6];
    const float* w_hh1  = (const float*)d_in[7];
    const float* b_ih1  = (const float*)d_in[8];
    const float* b_hh1  = (const float*)d_in[9];
    const float* w_ih2  = (const float*)d_in[10];
    const float* w_hh2  = (const float*)d_in[11];
    const float* b_ih2  = (const float*)d_in[12];
    const float* b_hh2  = (const float*)d_in[13];
    float* out = (float*)d_out;

    bump_gen_kernel<<<1, 32>>>();

    gemm_bias<0><<<dim3(4 * HID / 64, NCLS / 128), 256>>>(embed, w_ih0, b_ih0, b_hh0,
                                                          NCLS, 4 * HID, HID);
    lstm_scan0<<<HID / 8, 256>>>(w_hh0, tokens);

    gemm_bias<1><<<dim3(4 * HID / 64, SEQ / 128), 256>>>(nullptr, w_ih1, b_ih1, b_hh1,
                                                         SEQ, 4 * HID, HID);
    // layer1 (128 CTAs) + layer2 (16 spare-SM CTAs, backoff pollers)
    lstm_scan12<<<144, 256>>>(w_hh1, w_ih2, w_hh2, b_ih2, b_hh2, out);

    finalize_kernel<<<18, 256>>>(out);
}

// round 14
// speedup vs baseline: 1.4757x; 1.4757x over previous
#include <cuda_runtime.h>
#include <cstdint>

#define SEQ  4096
#define HID  1024
#define NCLS 256

typedef unsigned long long ull;

// ---------------- scratch (device globals: allocation-free) ----------------
__device__ float g_table[NCLS * 4 * HID];   //  4 MB  pre-activation table for layer0
__device__ float g_pre1 [SEQ  * 4 * HID];   // 64 MB  pre for layer1
__device__ float g_pre2 [SEQ  * 4 * NCLS];  // 16 MB  pre for layer2
__device__ float g_hs0  [SEQ * HID];        // 16 MB  plain h (GEMM input / finals)
__device__ float g_hs1  [SEQ * HID];        // 16 MB
__device__ ull   g_tg0  [SEQ * HID];        // 32 MB  tagged h for recurrence handoff
__device__ ull   g_tg1  [SEQ * HID];        // 32 MB
__device__ ull   g_tg2  [SEQ * NCLS];       //  8 MB
__device__ float g_cfin [2 * HID + NCLS];   // c0, c1, c2 finals
__device__ unsigned int g_gen;              // per-launch generation for tags

// ---------------- helpers (R3-original) ----------------
__device__ __forceinline__ float fsig(float x) {
    return __fdividef(1.0f, 1.0f + __expf(-x));
}
__device__ __forceinline__ float ftanh(float x) {
    float a = fabsf(x);
    float e = __expf(2.0f * a);
    float r = 1.0f - __fdividef(2.0f, e + 1.0f);   // (e-1)/(e+1), overflow-safe
    return copysignf(r, x);
}
__device__ __forceinline__ ull ld_tag(const ull* p) {
    ull v;
    asm volatile("ld.relaxed.gpu.global.b64 %0, [%1];" : "=l"(v) : "l"(p) : "memory");
    return v;
}
__device__ __forceinline__ void st_tag(ull* p, ull v) {
    asm volatile("st.relaxed.gpu.global.b64 [%0], %1;" :: "l"(p), "l"(v) : "memory");
}
// packed dual-fp32 FMA (B300 f32x2 pipe)
__device__ __forceinline__ ull fma2(ull a, ull b, ull c) {
    ull d;
    asm("fma.rn.f32x2 %0, %1, %2, %3;" : "=l"(d) : "l"(a), "l"(b), "l"(c));
    return d;
}
__device__ __forceinline__ float lo32(ull v) { return __uint_as_float((unsigned)v); }
__device__ __forceinline__ float hi32(ull v) { return __uint_as_float((unsigned)(v >> 32)); }

__global__ void bump_gen_kernel() { if (threadIdx.x == 0) g_gen += 1u; }

// ---------------- GEMM:  C = A @ B^T + b1 + b2  (128x128 tile, 8x8/thread) -
// SINGLE CHANGE THIS ROUND. 256 threads; each owns an 8x8 accumulator block.
// Per kk: 4 LDS.128 per 64 FMA (16:1) -> FMA-bound instead of LDS-bound.
template<int WHICH>
__global__ void __launch_bounds__(256)
gemm_bias(const float* __restrict__ Ain, const float* __restrict__ B,
          const float* __restrict__ b1, const float* __restrict__ b2,
          int M, int N, int K)
{
    const float* A = (WHICH == 1) ? g_hs0 : (WHICH == 2) ? g_hs1 : Ain;
    float*       C = (WHICH == 0) ? g_table : (WHICH == 1) ? g_pre1 : g_pre2;

    __shared__ float As[16][136];
    __shared__ float Bs[16][136];

    const int m0 = blockIdx.y * 128;
    const int n0 = blockIdx.x * 128;
    const int tid = threadIdx.x;
    const int tm = tid >> 4;          // 0..15 -> 8 rows each
    const int tn = tid & 15;          // 0..15 -> 8 cols each
    const int lr = tid >> 1;          // 0..127  row being loaded (A and B)
    const int lk = (tid & 1) * 8;     // 0 or 8  k-offset (2 float4s)

    float acc[8][8];
#pragma unroll
    for (int i = 0; i < 8; i++)
#pragma unroll
        for (int j = 0; j < 8; j++) acc[i][j] = 0.0f;

    for (int kt = 0; kt < K; kt += 16) {
        float4 a0 = *reinterpret_cast<const float4*>(&A[(size_t)(m0 + lr) * K + kt + lk]);
        float4 a1 = *reinterpret_cast<const float4*>(&A[(size_t)(m0 + lr) * K + kt + lk + 4]);
        float4 b0 = *reinterpret_cast<const float4*>(&B[(size_t)(n0 + lr) * K + kt + lk]);
        float4 b1v = *reinterpret_cast<const float4*>(&B[(size_t)(n0 + lr) * K + kt + lk + 4]);
        __syncthreads();
        As[lk + 0][lr] = a0.x; As[lk + 1][lr] = a0.y; As[lk + 2][lr] = a0.z; As[lk + 3][lr] = a0.w;
        As[lk + 4][lr] = a1.x; As[lk + 5][lr] = a1.y; As[lk + 6][lr] = a1.z; As[lk + 7][lr] = a1.w;
        Bs[lk + 0][lr] = b0.x; Bs[lk + 1][lr] = b0.y; Bs[lk + 2][lr] = b0.z; Bs[lk + 3][lr] = b0.w;
        Bs[lk + 4][lr] = b1v.x; Bs[lk + 5][lr] = b1v.y; Bs[lk + 6][lr] = b1v.z; Bs[lk + 7][lr] = b1v.w;
        __syncthreads();
#pragma unroll
        for (int kk = 0; kk < 16; kk++) {
            float4 a4 = *reinterpret_cast<const float4*>(&As[kk][tm * 8]);
            float4 a5 = *reinterpret_cast<const float4*>(&As[kk][tm * 8 + 4]);
            float4 b4 = *reinterpret_cast<const float4*>(&Bs[kk][tn * 8]);
            float4 b5 = *reinterpret_cast<const float4*>(&Bs[kk][tn * 8 + 4]);
            float a[8] = {a4.x, a4.y, a4.z, a4.w, a5.x, a5.y, a5.z, a5.w};
            float b[8] = {b4.x, b4.y, b4.z, b4.w, b5.x, b5.y, b5.z, b5.w};
#pragma unroll
            for (int i = 0; i < 8; i++)
#pragma unroll
                for (int j = 0; j < 8; j++) acc[i][j] += a[i] * b[j];
        }
    }

    const int col0 = n0 + tn * 8;
    float4 u1 = *reinterpret_cast<const float4*>(&b1[col0]);
    float4 u2 = *reinterpret_cast<const float4*>(&b2[col0]);
    float4 u3 = *reinterpret_cast<const float4*>(&b1[col0 + 4]);
    float4 u4 = *reinterpret_cast<const float4*>(&b2[col0 + 4]);
    float bias[8] = {u1.x + u2.x, u1.y + u2.y, u1.z + u2.z, u1.w + u2.w,
                     u3.x + u4.x, u3.y + u4.y, u3.z + u4.z, u3.w + u4.w};
#pragma unroll
    for (int i = 0; i < 8; i++) {
        int row = m0 + tm * 8 + i;
        float4 o0, o1;
        o0.x = acc[i][0] + bias[0]; o0.y = acc[i][1] + bias[1];
        o0.z = acc[i][2] + bias[2]; o0.w = acc[i][3] + bias[3];
        o1.x = acc[i][4] + bias[4]; o1.y = acc[i][5] + bias[5];
        o1.z = acc[i][6] + bias[6]; o1.w = acc[i][7] + bias[7];
        *reinterpret_cast<float4*>(&C[(size_t)row * N + col0]) = o0;
        *reinterpret_cast<float4*>(&C[(size_t)row * N + col0 + 4]) = o1;
    }
}

// ---------------- LSTM scan (R3 bytes, FROZEN — no nanosleep) --------------
template<int INDIM, int OUTDIM, int LAYER>
__global__ void __launch_bounds__(256, 1)
lstm_scan(const float* __restrict__ whh,       // [4*OUTDIM][INDIM]
          const int*   __restrict__ tokens,    // layer 0 only
          float*       __restrict__ hs_param)  // layer 2: d_out
{
    constexpr int KITER = INDIM / 128;   // 8 (HID) or 2 (NCLS)
    constexpr int PPT   = INDIM / 256;   // tagged words staged per thread

    const float* pre = (LAYER == 0) ? g_table : (LAYER == 1) ? g_pre1 : g_pre2;
    ull*   tg = (LAYER == 0) ? g_tg0 : (LAYER == 1) ? g_tg1 : g_tg2;
    float* hs = (LAYER == 0) ? g_hs0 : (LAYER == 1) ? g_hs1 : hs_param;
    float* cf = g_cfin + ((LAYER == 0) ? 0 : (LAYER == 1) ? HID : 2 * HID);

    const int tid = threadIdx.x;
    const int w = tid >> 5;
    const int l = tid & 31;
    const int out = blockIdx.x * 8 + w;
    const unsigned tb = g_gen * (unsigned)(SEQ + 1);

    __shared__ __align__(16) float sh[2][INDIM];
    __shared__ int stok[(LAYER == 0) ? SEQ : 1];

    // register-resident weights: 4 gate rows, this lane's k-slices
    ulonglong2 wq[4][KITER];
#pragma unroll
    for (int r = 0; r < 4; r++)
#pragma unroll
        for (int i = 0; i < KITER; i++)
            wq[r][i] = *reinterpret_cast<const ulonglong2*>(
                whh + (size_t)(r * OUTDIM + out) * INDIM + i * 128 + 4 * l);

    if constexpr (LAYER == 0) {
        for (int i = tid; i < SEQ; i += 256) stok[i] = tokens[i];
    }
    for (int i = tid; i < INDIM; i += 256) sh[0][i] = 0.0f;
    __syncthreads();

    auto loadpre = [&](int tt, int r) -> float {
        if constexpr (LAYER == 0)
            return __ldg(&pre[(size_t)stok[tt] * (4 * OUTDIM) + r * OUTDIM + out]);
        else
            return __ldg(&pre[(size_t)tt * (4 * OUTDIM) + r * OUTDIM + out]);
    };

    float c = 0.0f;
    float pv = (l < 4) ? loadpre(0, l) : 0.0f;

    for (int t = 0; t < SEQ; t++) {
        float pvn = (l < 4 && t + 1 < SEQ) ? loadpre(t + 1, l) : 0.0f;

        float* shb = sh[t & 1];
        if (t > 0) {
            const ull* src = tg + (size_t)(t - 1) * INDIM;
            const unsigned expect = tb + (unsigned)t;   // producer wrote tb + (t-1) + 1
            ull v[PPT];
            // parallel batch poll: all PPT loads in flight simultaneously
#pragma unroll
            for (int j = 0; j < PPT; j++) v[j] = ld_tag(src + tid + 256 * j);
            while (true) {
                bool ok = true;
#pragma unroll
                for (int j = 0; j < PPT; j++) ok &= ((unsigned)(v[j] >> 32) == expect);
                if (ok) break;
#pragma unroll
                for (int j = 0; j < PPT; j++) v[j] = ld_tag(src + tid + 256 * j);
            }
#pragma unroll
            for (int j = 0; j < PPT; j++)
                shb[tid + 256 * j] = __uint_as_float((unsigned)v[j]);
        }
        __syncthreads();

        // 4 gate-row dot products, packed f32x2 FMA
        ull acc[4] = {0ull, 0ull, 0ull, 0ull};
#pragma unroll
        for (int i = 0; i < KITER; i++) {
            ulonglong2 hv = *reinterpret_cast<const ulonglong2*>(shb + i * 128 + 4 * l);
#pragma unroll
            for (int r = 0; r < 4; r++) {
                acc[r] = fma2(wq[r][i].x, hv.x, acc[r]);
                acc[r] = fma2(wq[r][i].y, hv.y, acc[r]);
            }
        }
        float g[4];
#pragma unroll
        for (int r = 0; r < 4; r++) g[r] = lo32(acc[r]) + hi32(acc[r]);
#pragma unroll
        for (int s = 16; s > 0; s >>= 1)
#pragma unroll
            for (int r = 0; r < 4; r++) g[r] += __shfl_xor_sync(0xffffffffu, g[r], s);

        const float p0 = __shfl_sync(0xffffffffu, pv, 0);
        const float p1 = __shfl_sync(0xffffffffu, pv, 1);
        const float p2 = __shfl_sync(0xffffffffu, pv, 2);
        const float p3 = __shfl_sync(0xffffffffu, pv, 3);

        c = fsig(g[1] + p1) * c + fsig(g[0] + p0) * ftanh(g[2] + p2);
        const float h = fsig(g[3] + p3) * ftanh(c);

        if (l == 0) {
            st_tag(tg + (size_t)t * OUTDIM + out,
                   ((ull)(tb + (unsigned)t + 1u) << 32) | (ull)__float_as_uint(h));
            hs[(size_t)t * OUTDIM + out] = h;
            if (t == SEQ - 1) cf[out] = c;
        }
        pv = pvn;
    }
}

// ---------------- final output assembly ----------------
__global__ void finalize_kernel(float* __restrict__ out) {
    int i = blockIdx.x * blockDim.x + threadIdx.x;
    const int OB = SEQ * NCLS;   // 1048576: start of h_stack
    if (i < 1024)      out[OB + i] = g_hs0[(SEQ - 1) * HID + i];
    else if (i < 2048) out[OB + i] = g_hs1[(SEQ - 1) * HID + (i - 1024)];
    else if (i < 3072) out[OB + i] = g_cfin[i - 2048];                   // c0
    else if (i < 4096) out[OB + i] = g_cfin[HID + (i - 3072)];           // c1
    else if (i < 4352) out[OB + i] = out[(SEQ - 1) * NCLS + (i - 4096)]; // h2
    else if (i < 4608) out[OB + i] = g_cfin[2 * HID + (i - 4352)];       // c2
}

// ---------------- launch ----------------
extern "C" void kernel_launch(void* const* d_in, const int* in_sizes, int n_in,
                              void* d_out, int out_size)
{
    const int*   tokens = (const int*)  d_in[0];
    const float* embed  = (const float*)d_in[1];
    const float* w_ih0  = (const float*)d_in[2];
    const float* w_hh0  = (const float*)d_in[3];
    const float* b_ih0  = (const float*)d_in[4];
    const float* b_hh0  = (const float*)d_in[5];
    const float* w_ih1  = (const float*)d_in[6];
    const float* w_hh1  = (const float*)d_in[7];
    const float* b_ih1  = (const float*)d_in[8];
    const float* b_hh1  = (const float*)d_in[9];
    const float* w_ih2  = (const float*)d_in[10];
    const float* w_hh2  = (const float*)d_in[11];
    const float* b_ih2  = (const float*)d_in[12];
    const float* b_hh2  = (const float*)d_in[13];
    float* out = (float*)d_out;

    bump_gen_kernel<<<1, 32>>>();

    // layer 0 pre-activation table: [256 classes][4096 gate rows]
    gemm_bias<0><<<dim3(4 * HID / 128, NCLS / 128), 256>>>(embed, w_ih0, b_ih0, b_hh0,
                                                           NCLS, 4 * HID, HID);
    lstm_scan<HID, HID, 0><<<HID / 8, 256>>>(w_hh0, tokens, nullptr);

    gemm_bias<1><<<dim3(4 * HID / 128, SEQ / 128), 256>>>(nullptr, w_ih1, b_ih1, b_hh1,
                                                          SEQ, 4 * HID, HID);
    lstm_scan<HID, HID, 1><<<HID / 8, 256>>>(w_hh1, nullptr, nullptr);

    gemm_bias<2><<<dim3(4 * NCLS / 128, SEQ / 128), 256>>>(nullptr, w_ih2, b_ih2, b_hh2,
                                                           SEQ, 4 * NCLS, HID);
    lstm_scan<NCLS, NCLS, 2><<<NCLS / 8, 256>>>(w_hh2, nullptr, out);

    finalize_kernel<<<18, 256>>>(out);
}

// round 16
// speedup vs baseline: 1.4814x; 1.0039x over previous
#include <cuda_runtime.h>
#include <cstdint>

#define SEQ  4096
#define HID  1024
#define NCLS 256

typedef unsigned long long ull;

// ---------------- scratch (device globals: allocation-free) ----------------
__device__ float g_table[NCLS * 4 * HID];   //  4 MB  pre-activation table for layer0
__device__ float g_pre1 [SEQ  * 4 * HID];   // 64 MB  pre for layer1
__device__ float g_pre2 [SEQ  * 4 * NCLS];  // 16 MB  pre for layer2
__device__ float g_hs0  [SEQ * HID];        // 16 MB  plain h (GEMM input / finals)
__device__ float g_hs1  [SEQ * HID];        // 16 MB
__device__ ull   g_tg0  [SEQ * HID];        // 32 MB  tagged h for recurrence handoff
__device__ ull   g_tg1  [SEQ * HID];        // 32 MB
__device__ float g_cfin [2 * HID + NCLS];   // c0, c1, c2 finals
__device__ unsigned int g_gen;              // per-launch generation for tags

// ---------------- helpers (R3-original) ----------------
__device__ __forceinline__ float fsig(float x) {
    return __fdividef(1.0f, 1.0f + __expf(-x));
}
__device__ __forceinline__ float ftanh(float x) {
    float a = fabsf(x);
    float e = __expf(2.0f * a);
    float r = 1.0f - __fdividef(2.0f, e + 1.0f);   // (e-1)/(e+1), overflow-safe
    return copysignf(r, x);
}
__device__ __forceinline__ ull ld_tag(const ull* p) {
    ull v;
    asm volatile("ld.relaxed.gpu.global.b64 %0, [%1];" : "=l"(v) : "l"(p) : "memory");
    return v;
}
__device__ __forceinline__ void st_tag(ull* p, ull v) {
    asm volatile("st.relaxed.gpu.global.b64 [%0], %1;" :: "l"(p), "l"(v) : "memory");
}
// packed dual-fp32 FMA (B300 f32x2 pipe)
__device__ __forceinline__ ull fma2(ull a, ull b, ull c) {
    ull d;
    asm("fma.rn.f32x2 %0, %1, %2, %3;" : "=l"(d) : "l"(a), "l"(b), "l"(c));
    return d;
}
__device__ __forceinline__ ull add2(ull a, ull b) {
    ull d;
    asm("add.rn.f32x2 %0, %1, %2;" : "=l"(d) : "l"(a), "l"(b));
    return d;
}
__device__ __forceinline__ ull pack2(float lo, float hi) {
    ull d;
    asm("mov.b64 %0, {%1, %2};" : "=l"(d) : "f"(lo), "f"(hi));
    return d;
}
__device__ __forceinline__ float lo32(ull v) { return __uint_as_float((unsigned)v); }
__device__ __forceinline__ float hi32(ull v) { return __uint_as_float((unsigned)(v >> 32)); }

__device__ __forceinline__ uint32_t smem_u32(const void* p) {
    uint32_t a;
    asm("{ .reg .u64 t; cvta.to.shared.u64 t, %1; cvt.u32.u64 %0, t; }" : "=r"(a) : "l"(p));
    return a;
}
// store float into another cluster CTA's SMEM at the same offset
__device__ __forceinline__ void st_dsmem(uint32_t local_addr, uint32_t rank, float v) {
    asm volatile(
        "{\n\t"
        ".reg .b32 r;\n\t"
        "mapa.shared::cluster.u32 r, %0, %1;\n\t"
        "st.shared::cluster.f32 [r], %2;\n\t"
        "}" :: "r"(local_addr), "r"(rank), "f"(v) : "memory");
}

__global__ void bump_gen_kernel() { if (threadIdx.x == 0) g_gen += 1u; }

// ---------------- GEMM (R14 bytes): 128x128 tile, 8x8/thread ----------------
template<int WHICH>
__global__ void __launch_bounds__(256)
gemm_bias(const float* __restrict__ Ain, const float* __restrict__ B,
          const float* __restrict__ b1, const float* __restrict__ b2,
          int M, int N, int K)
{
    const float* A = (WHICH == 1) ? g_hs0 : (WHICH == 2) ? g_hs1 : Ain;
    float*       C = (WHICH == 0) ? g_table : (WHICH == 1) ? g_pre1 : g_pre2;

    __shared__ float As[16][136];
    __shared__ float Bs[16][136];

    const int m0 = blockIdx.y * 128;
    const int n0 = blockIdx.x * 128;
    const int tid = threadIdx.x;
    const int tm = tid >> 4;
    const int tn = tid & 15;
    const int lr = tid >> 1;
    const int lk = (tid & 1) * 8;

    float acc[8][8];
#pragma unroll
    for (int i = 0; i < 8; i++)
#pragma unroll
        for (int j = 0; j < 8; j++) acc[i][j] = 0.0f;

    for (int kt = 0; kt < K; kt += 16) {
        float4 a0 = *reinterpret_cast<const float4*>(&A[(size_t)(m0 + lr) * K + kt + lk]);
        float4 a1 = *reinterpret_cast<const float4*>(&A[(size_t)(m0 + lr) * K + kt + lk + 4]);
        float4 b0 = *reinterpret_cast<const float4*>(&B[(size_t)(n0 + lr) * K + kt + lk]);
        float4 b1v = *reinterpret_cast<const float4*>(&B[(size_t)(n0 + lr) * K + kt + lk + 4]);
        __syncthreads();
        As[lk + 0][lr] = a0.x; As[lk + 1][lr] = a0.y; As[lk + 2][lr] = a0.z; As[lk + 3][lr] = a0.w;
        As[lk + 4][lr] = a1.x; As[lk + 5][lr] = a1.y; As[lk + 6][lr] = a1.z; As[lk + 7][lr] = a1.w;
        Bs[lk + 0][lr] = b0.x; Bs[lk + 1][lr] = b0.y; Bs[lk + 2][lr] = b0.z; Bs[lk + 3][lr] = b0.w;
        Bs[lk + 4][lr] = b1v.x; Bs[lk + 5][lr] = b1v.y; Bs[lk + 6][lr] = b1v.z; Bs[lk + 7][lr] = b1v.w;
        __syncthreads();
#pragma unroll
        for (int kk = 0; kk < 16; kk++) {
            float4 a4 = *reinterpret_cast<const float4*>(&As[kk][tm * 8]);
            float4 a5 = *reinterpret_cast<const float4*>(&As[kk][tm * 8 + 4]);
            float4 b4 = *reinterpret_cast<const float4*>(&Bs[kk][tn * 8]);
            float4 b5 = *reinterpret_cast<const float4*>(&Bs[kk][tn * 8 + 4]);
            float a[8] = {a4.x, a4.y, a4.z, a4.w, a5.x, a5.y, a5.z, a5.w};
            float b[8] = {b4.x, b4.y, b4.z, b4.w, b5.x, b5.y, b5.z, b5.w};
#pragma unroll
            for (int i = 0; i < 8; i++)
#pragma unroll
                for (int j = 0; j < 8; j++) acc[i][j] += a[i] * b[j];
        }
    }

    const int col0 = n0 + tn * 8;
    float4 u1 = *reinterpret_cast<const float4*>(&b1[col0]);
    float4 u2 = *reinterpret_cast<const float4*>(&b2[col0]);
    float4 u3 = *reinterpret_cast<const float4*>(&b1[col0 + 4]);
    float4 u4 = *reinterpret_cast<const float4*>(&b2[col0 + 4]);
    float bias[8] = {u1.x + u2.x, u1.y + u2.y, u1.z + u2.z, u1.w + u2.w,
                     u3.x + u4.x, u3.y + u4.y, u3.z + u4.z, u3.w + u4.w};
#pragma unroll
    for (int i = 0; i < 8; i++) {
        int row = m0 + tm * 8 + i;
        float4 o0, o1;
        o0.x = acc[i][0] + bias[0]; o0.y = acc[i][1] + bias[1];
        o0.z = acc[i][2] + bias[2]; o0.w = acc[i][3] + bias[3];
        o1.x = acc[i][4] + bias[4]; o1.y = acc[i][5] + bias[5];
        o1.z = acc[i][6] + bias[6]; o1.w = acc[i][7] + bias[7];
        *reinterpret_cast<float4*>(&C[(size_t)row * N + col0]) = o0;
        *reinterpret_cast<float4*>(&C[(size_t)row * N + col0 + 4]) = o1;
    }
}

// ---------------- LSTM scan layers 0/1 (R3 bytes, FROZEN) ------------------
template<int INDIM, int OUTDIM, int LAYER>
__global__ void __launch_bounds__(256, 1)
lstm_scan(const float* __restrict__ whh,       // [4*OUTDIM][INDIM]
          const int*   __restrict__ tokens,    // layer 0 only
          float*       __restrict__ hs_param)  // unused here
{
    constexpr int KITER = INDIM / 128;
    constexpr int PPT   = INDIM / 256;

    const float* pre = (LAYER == 0) ? g_table : g_pre1;
    ull*   tg = (LAYER == 0) ? g_tg0 : g_tg1;
    float* hs = (LAYER == 0) ? g_hs0 : g_hs1;
    float* cf = g_cfin + ((LAYER == 0) ? 0 : HID);

    const int tid = threadIdx.x;
    const int w = tid >> 5;
    const int l = tid & 31;
    const int out = blockIdx.x * 8 + w;
    const unsigned tb = g_gen * (unsigned)(SEQ + 1);

    __shared__ __align__(16) float sh[2][INDIM];
    __shared__ int stok[(LAYER == 0) ? SEQ : 1];

    ulonglong2 wq[4][KITER];
#pragma unroll
    for (int r = 0; r < 4; r++)
#pragma unroll
        for (int i = 0; i < KITER; i++)
            wq[r][i] = *reinterpret_cast<const ulonglong2*>(
                whh + (size_t)(r * OUTDIM + out) * INDIM + i * 128 + 4 * l);

    if constexpr (LAYER == 0) {
        for (int i = tid; i < SEQ; i += 256) stok[i] = tokens[i];
    }
    for (int i = tid; i < INDIM; i += 256) sh[0][i] = 0.0f;
    __syncthreads();

    auto loadpre = [&](int tt, int r) -> float {
        if constexpr (LAYER == 0)
            return __ldg(&pre[(size_t)stok[tt] * (4 * OUTDIM) + r * OUTDIM + out]);
        else
            return __ldg(&pre[(size_t)tt * (4 * OUTDIM) + r * OUTDIM + out]);
    };

    float c = 0.0f;
    float pv = (l < 4) ? loadpre(0, l) : 0.0f;

    for (int t = 0; t < SEQ; t++) {
        float pvn = (l < 4 && t + 1 < SEQ) ? loadpre(t + 1, l) : 0.0f;

        float* shb = sh[t & 1];
        if (t > 0) {
            const ull* src = tg + (size_t)(t - 1) * INDIM;
            const unsigned expect = tb + (unsigned)t;
            ull v[PPT];
#pragma unroll
            for (int j = 0; j < PPT; j++) v[j] = ld_tag(src + tid + 256 * j);
            while (true) {
                bool ok = true;
#pragma unroll
                for (int j = 0; j < PPT; j++) ok &= ((unsigned)(v[j] >> 32) == expect);
                if (ok) break;
#pragma unroll
                for (int j = 0; j < PPT; j++) v[j] = ld_tag(src + tid + 256 * j);
            }
#pragma unroll
            for (int j = 0; j < PPT; j++)
                shb[tid + 256 * j] = __uint_as_float((unsigned)v[j]);
        }
        __syncthreads();

        ull acc[4] = {0ull, 0ull, 0ull, 0ull};
#pragma unroll
        for (int i = 0; i < KITER; i++) {
            ulonglong2 hv = *reinterpret_cast<const ulonglong2*>(shb + i * 128 + 4 * l);
#pragma unroll
            for (int r = 0; r < 4; r++) {
                acc[r] = fma2(wq[r][i].x, hv.x, acc[r]);
                acc[r] = fma2(wq[r][i].y, hv.y, acc[r]);
            }
        }
        float g[4];
#pragma unroll
        for (int r = 0; r < 4; r++) g[r] = lo32(acc[r]) + hi32(acc[r]);
#pragma unroll
        for (int s = 16; s > 0; s >>= 1)
#pragma unroll
            for (int r = 0; r < 4; r++) g[r] += __shfl_xor_sync(0xffffffffu, g[r], s);

        const float p0 = __shfl_sync(0xffffffffu, pv, 0);
        const float p1 = __shfl_sync(0xffffffffu, pv, 1);
        const float p2 = __shfl_sync(0xffffffffu, pv, 2);
        const float p3 = __shfl_sync(0xffffffffu, pv, 3);

        c = fsig(g[1] + p1) * c + fsig(g[0] + p0) * ftanh(g[2] + p2);
        const float h = fsig(g[3] + p3) * ftanh(c);

        if (l == 0) {
            st_tag(tg + (size_t)t * OUTDIM + out,
                   ((ull)(tb + (unsigned)t + 1u) << 32) | (ull)__float_as_uint(h));
            hs[(size_t)t * OUTDIM + out] = h;
            if (t == SEQ - 1) cf[out] = c;
        }
        pv = pvn;
    }
}

// ---------------- layer-2 scan: ONE 8-CTA CLUSTER, DSMEM handoff -----------
// 8 CTAs x 256 thr, cluster(8). CTA rank owns outputs [rank*32, rank*32+32).
// Warp w owns 4 outputs (group g = lane>>3); lane j = lane&7 covers
// k = 4*j + 32*i (i<8). h2 broadcast: writer pushes h into ALL 8 CTAs' SMEM
// (mapa + st.shared::cluster), one cluster barrier per step. No L2, no tags.
// FIX vs R15: pre2 already contains b_ih2+b_hh2 (added by gemm_bias<2>) —
// do NOT add bias again here.
__global__ void __cluster_dims__(8, 1, 1) __launch_bounds__(256, 1)
lstm_scan2_cluster(const float* __restrict__ whh, float* __restrict__ outp)
{
    const int tid = threadIdx.x;
    const int w = tid >> 5;
    const int l = tid & 31;
    const int g = l >> 3;
    const int j = l & 7;
    uint32_t rank;
    asm("mov.u32 %0, %%cluster_ctarank;" : "=r"(rank));
    const int o = (int)rank * 32 + w * 4 + g;

    __shared__ __align__(16) float sh2[2][NCLS];
    const uint32_t sh2_base = smem_u32(&sh2[0][0]);

    // weights: 4 gate rows x 8 chunks of 4 floats (128 regs)
    ulonglong2 wq[4][8];
#pragma unroll
    for (int r = 0; r < 4; r++)
#pragma unroll
        for (int i = 0; i < 8; i++)
            wq[r][i] = *reinterpret_cast<const ulonglong2*>(
                whh + (size_t)(r * NCLS + o) * NCLS + 32 * i + 4 * j);

    for (int i = tid; i < NCLS; i += 256) sh2[0][i] = 0.0f;   // h2_{-1} = 0
    __syncthreads();

    float c = 0.0f;
    float pv[4];
#pragma unroll
    for (int r = 0; r < 4; r++)
        pv[r] = __ldg(&g_pre2[(size_t)0 * (4 * NCLS) + r * NCLS + o]);

    for (int t = 0; t < SEQ; t++) {
        float pvn[4] = {0.f, 0.f, 0.f, 0.f};
        if (t + 1 < SEQ) {
#pragma unroll
            for (int r = 0; r < 4; r++)
                pvn[r] = __ldg(&g_pre2[(size_t)(t + 1) * (4 * NCLS) + r * NCLS + o]);
        }

        const float* shb = sh2[t & 1];
        ull acc[4] = {0ull, 0ull, 0ull, 0ull};
#pragma unroll
        for (int i = 0; i < 8; i++) {
            ulonglong2 hv = *reinterpret_cast<const ulonglong2*>(shb + 32 * i + 4 * j);
#pragma unroll
            for (int r = 0; r < 4; r++) {
                acc[r] = fma2(wq[r][i].x, hv.x, acc[r]);
                acc[r] = fma2(wq[r][i].y, hv.y, acc[r]);
            }
        }
        // 3-stage butterfly within the 8-lane group (packed f32x2);
        // all 8 lanes end with all 4 gate sums
        ull p01 = pack2(lo32(acc[0]) + hi32(acc[0]), lo32(acc[1]) + hi32(acc[1]));
        ull p23 = pack2(lo32(acc[2]) + hi32(acc[2]), lo32(acc[3]) + hi32(acc[3]));
#pragma unroll
        for (int s = 4; s > 0; s >>= 1) {
            p01 = add2(p01, __shfl_xor_sync(0xffffffffu, p01, s));
            p23 = add2(p23, __shfl_xor_sync(0xffffffffu, p23, s));
        }
        const float s0 = lo32(p01) + pv[0];   // i  (pre2 already has biases)
        const float s1 = hi32(p01) + pv[1];   // f
        const float s2 = lo32(p23) + pv[2];   // g
        const float s3 = hi32(p23) + pv[3];   // o

        c = fsig(s1) * c + fsig(s0) * ftanh(s2);
        const float h = fsig(s3) * ftanh(c);

        if (j == 0) {
            outp[(size_t)t * NCLS + o] = h;
            if (t == SEQ - 1) g_cfin[2 * HID + o] = c;
            // push h into next-step buffer of every cluster CTA
            const uint32_t dst = sh2_base + (uint32_t)((((t + 1) & 1) * NCLS + o) * 4);
#pragma unroll
            for (uint32_t rk = 0; rk < 8; rk++) st_dsmem(dst, rk, h);
        }
        // release DSMEM stores / acquire peers' stores
        asm volatile("barrier.cluster.arrive.aligned;" ::: "memory");
        asm volatile("barrier.cluster.wait.aligned;" ::: "memory");

#pragma unroll
        for (int r = 0; r < 4; r++) pv[r] = pvn[r];
    }
}

// ---------------- final output assembly ----------------
__global__ void finalize_kernel(float* __restrict__ out) {
    int i = blockIdx.x * blockDim.x + threadIdx.x;
    const int OB = SEQ * NCLS;   // 1048576: start of h_stack
    if (i < 1024)      out[OB + i] = g_hs0[(SEQ - 1) * HID + i];
    else if (i < 2048) out[OB + i] = g_hs1[(SEQ - 1) * HID + (i - 1024)];
    else if (i < 3072) out[OB + i] = g_cfin[i - 2048];                   // c0
    else if (i < 4096) out[OB + i] = g_cfin[HID + (i - 3072)];           // c1
    else if (i < 4352) out[OB + i] = out[(SEQ - 1) * NCLS + (i - 4096)]; // h2
    else if (i < 4608) out[OB + i] = g_cfin[2 * HID + (i - 4352)];       // c2
}

// ---------------- launch ----------------
extern "C" void kernel_launch(void* const* d_in, const int* in_sizes, int n_in,
                              void* d_out, int out_size)
{
    const int*   tokens = (const int*)  d_in[0];
    const float* embed  = (const float*)d_in[1];
    const float* w_ih0  = (const float*)d_in[2];
    const float* w_hh0  = (const float*)d_in[3];
    const float* b_ih0  = (const float*)d_in[4];
    const float* b_hh0  = (const float*)d_in[5];
    const float* w_ih1  = (const float*)d_in[6];
    const float* w_hh1  = (const float*)d_in[7];
    const float* b_ih1  = (const float*)d_in[8];
    const float* b_hh1  = (const float*)d_in[9];
    const float* w_ih2  = (const float*)d_in[10];
    const float* w_hh2  = (const float*)d_in[11];
    const float* b_ih2  = (const float*)d_in[12];
    const float* b_hh2  = (const float*)d_in[13];
    float* out = (float*)d_out;

    bump_gen_kernel<<<1, 32>>>();

    // layer 0 pre-activation table: [256 classes][4096 gate rows]
    gemm_bias<0><<<dim3(4 * HID / 128, NCLS / 128), 256>>>(embed, w_ih0, b_ih0, b_hh0,
                                                           NCLS, 4 * HID, HID);
    lstm_scan<HID, HID, 0><<<HID / 8, 256>>>(w_hh0, tokens, nullptr);

    gemm_bias<1><<<dim3(4 * HID / 128, SEQ / 128), 256>>>(nullptr, w_ih1, b_ih1, b_hh1,
                                                          SEQ, 4 * HID, HID);
    lstm_scan<HID, HID, 1><<<HID / 8, 256>>>(w_hh1, nullptr, nullptr);

    gemm_bias<2><<<dim3(4 * NCLS / 128, SEQ / 128), 256>>>(nullptr, w_ih2, b_ih2, b_hh2,
                                                           SEQ, 4 * NCLS, HID);
    // layer 2: one 8-CTA cluster, DSMEM recurrence (replaces tagged-L2 scan)
    lstm_scan2_cluster<<<8, 256>>>(w_hh2, out);

    finalize_kernel<<<18, 256>>>(out);
}

// round 17
// speedup vs baseline: 1.4877x; 1.0042x over previous
#include <cuda_runtime.h>
#include <cstdint>

#define SEQ  4096
#define HID  1024
#define NCLS 256

typedef unsigned long long ull;

// ---------------- scratch (device globals: allocation-free) ----------------
__device__ float g_table[NCLS * 4 * HID];   //  4 MB  pre-activation table for layer0
__device__ float g_pre1 [SEQ  * 4 * HID];   // 64 MB  pre for layer1
__device__ float g_pre2 [SEQ  * 4 * NCLS];  // 16 MB  pre for layer2
__device__ float g_hs0  [SEQ * HID];        // 16 MB  plain h (GEMM input / finals)
__device__ float g_hs1  [SEQ * HID];        // 16 MB
__device__ ull   g_tg0  [SEQ * HID];        // 32 MB  tagged h for recurrence handoff
__device__ ull   g_tg1  [SEQ * HID];        // 32 MB
__device__ float g_cfin [2 * HID + NCLS];   // c0, c1, c2 finals
__device__ unsigned int g_gen;              // per-launch generation for tags

// ---------------- helpers (R3-original) ----------------
__device__ __forceinline__ float fsig(float x) {
    return __fdividef(1.0f, 1.0f + __expf(-x));
}
__device__ __forceinline__ float ftanh(float x) {
    float a = fabsf(x);
    float e = __expf(2.0f * a);
    float r = 1.0f - __fdividef(2.0f, e + 1.0f);   // (e-1)/(e+1), overflow-safe
    return copysignf(r, x);
}
__device__ __forceinline__ ull ld_tag(const ull* p) {
    ull v;
    asm volatile("ld.relaxed.gpu.global.b64 %0, [%1];" : "=l"(v) : "l"(p) : "memory");
    return v;
}
__device__ __forceinline__ void st_tag(ull* p, ull v) {
    asm volatile("st.relaxed.gpu.global.b64 [%0], %1;" :: "l"(p), "l"(v) : "memory");
}
// packed dual-fp32 FMA (B300 f32x2 pipe); bitwise == 2x fma.rn.f32
__device__ __forceinline__ ull fma2(ull a, ull b, ull c) {
    ull d;
    asm("fma.rn.f32x2 %0, %1, %2, %3;" : "=l"(d) : "l"(a), "l"(b), "l"(c));
    return d;
}
__device__ __forceinline__ ull add2(ull a, ull b) {
    ull d;
    asm("add.rn.f32x2 %0, %1, %2;" : "=l"(d) : "l"(a), "l"(b));
    return d;
}
__device__ __forceinline__ ull pack2(float lo, float hi) {
    ull d;
    asm("mov.b64 %0, {%1, %2};" : "=l"(d) : "f"(lo), "f"(hi));
    return d;
}
__device__ __forceinline__ float lo32(ull v) { return __uint_as_float((unsigned)v); }
__device__ __forceinline__ float hi32(ull v) { return __uint_as_float((unsigned)(v >> 32)); }

__device__ __forceinline__ uint32_t smem_u32(const void* p) {
    uint32_t a;
    asm("{ .reg .u64 t; cvta.to.shared.u64 t, %1; cvt.u32.u64 %0, t; }" : "=r"(a) : "l"(p));
    return a;
}
// store float into another cluster CTA's SMEM at the same offset
__device__ __forceinline__ void st_dsmem(uint32_t local_addr, uint32_t rank, float v) {
    asm volatile(
        "{\n\t"
        ".reg .b32 r;\n\t"
        "mapa.shared::cluster.u32 r, %0, %1;\n\t"
        "st.shared::cluster.f32 [r], %2;\n\t"
        "}" :: "r"(local_addr), "r"(rank), "f"(v) : "memory");
}

__global__ void bump_gen_kernel() { if (threadIdx.x == 0) g_gen += 1u; }

// ---------------- GEMM: 128x128 tile, 8x8/thread, PACKED f32x2 FMA ---------
// SINGLE CHANGE THIS ROUND: inner product uses fma.rn.f32x2 (B pairs read as
// ulonglong2 directly from SMEM; A splatted). Bitwise-identical results.
template<int WHICH>
__global__ void __launch_bounds__(256)
gemm_bias(const float* __restrict__ Ain, const float* __restrict__ B,
          const float* __restrict__ b1, const float* __restrict__ b2,
          int M, int N, int K)
{
    const float* A = (WHICH == 1) ? g_hs0 : (WHICH == 2) ? g_hs1 : Ain;
    float*       C = (WHICH == 0) ? g_table : (WHICH == 1) ? g_pre1 : g_pre2;

    __shared__ float As[16][136];
    __shared__ float Bs[16][136];

    const int m0 = blockIdx.y * 128;
    const int n0 = blockIdx.x * 128;
    const int tid = threadIdx.x;
    const int tm = tid >> 4;
    const int tn = tid & 15;
    const int lr = tid >> 1;
    const int lk = (tid & 1) * 8;

    ull acc2[8][4];
#pragma unroll
    for (int i = 0; i < 8; i++)
#pragma unroll
        for (int j = 0; j < 4; j++) acc2[i][j] = 0ull;

    for (int kt = 0; kt < K; kt += 16) {
        float4 a0 = *reinterpret_cast<const float4*>(&A[(size_t)(m0 + lr) * K + kt + lk]);
        float4 a1 = *reinterpret_cast<const float4*>(&A[(size_t)(m0 + lr) * K + kt + lk + 4]);
        float4 b0 = *reinterpret_cast<const float4*>(&B[(size_t)(n0 + lr) * K + kt + lk]);
        float4 b1v = *reinterpret_cast<const float4*>(&B[(size_t)(n0 + lr) * K + kt + lk + 4]);
        __syncthreads();
        As[lk + 0][lr] = a0.x; As[lk + 1][lr] = a0.y; As[lk + 2][lr] = a0.z; As[lk + 3][lr] = a0.w;
        As[lk + 4][lr] = a1.x; As[lk + 5][lr] = a1.y; As[lk + 6][lr] = a1.z; As[lk + 7][lr] = a1.w;
        Bs[lk + 0][lr] = b0.x; Bs[lk + 1][lr] = b0.y; Bs[lk + 2][lr] = b0.z; Bs[lk + 3][lr] = b0.w;
        Bs[lk + 4][lr] = b1v.x; Bs[lk + 5][lr] = b1v.y; Bs[lk + 6][lr] = b1v.z; Bs[lk + 7][lr] = b1v.w;
        __syncthreads();
#pragma unroll
        for (int kk = 0; kk < 16; kk++) {
            float4 a4 = *reinterpret_cast<const float4*>(&As[kk][tm * 8]);
            float4 a5 = *reinterpret_cast<const float4*>(&As[kk][tm * 8 + 4]);
            ulonglong2 bq0 = *reinterpret_cast<const ulonglong2*>(&Bs[kk][tn * 8]);
            ulonglong2 bq1 = *reinterpret_cast<const ulonglong2*>(&Bs[kk][tn * 8 + 4]);
            float a[8] = {a4.x, a4.y, a4.z, a4.w, a5.x, a5.y, a5.z, a5.w};
#pragma unroll
            for (int i = 0; i < 8; i++) {
                const ull av = pack2(a[i], a[i]);
                acc2[i][0] = fma2(av, bq0.x, acc2[i][0]);
                acc2[i][1] = fma2(av, bq0.y, acc2[i][1]);
                acc2[i][2] = fma2(av, bq1.x, acc2[i][2]);
                acc2[i][3] = fma2(av, bq1.y, acc2[i][3]);
            }
        }
    }

    const int col0 = n0 + tn * 8;
    float4 u1 = *reinterpret_cast<const float4*>(&b1[col0]);
    float4 u2 = *reinterpret_cast<const float4*>(&b2[col0]);
    float4 u3 = *reinterpret_cast<const float4*>(&b1[col0 + 4]);
    float4 u4 = *reinterpret_cast<const float4*>(&b2[col0 + 4]);
    float bias[8] = {u1.x + u2.x, u1.y + u2.y, u1.z + u2.z, u1.w + u2.w,
                     u3.x + u4.x, u3.y + u4.y, u3.z + u4.z, u3.w + u4.w};
#pragma unroll
    for (int i = 0; i < 8; i++) {
        int row = m0 + tm * 8 + i;
        float4 o0, o1;
        o0.x = lo32(acc2[i][0]) + bias[0]; o0.y = hi32(acc2[i][0]) + bias[1];
        o0.z = lo32(acc2[i][1]) + bias[2]; o0.w = hi32(acc2[i][1]) + bias[3];
        o1.x = lo32(acc2[i][2]) + bias[4]; o1.y = hi32(acc2[i][2]) + bias[5];
        o1.z = lo32(acc2[i][3]) + bias[6]; o1.w = hi32(acc2[i][3]) + bias[7];
        *reinterpret_cast<float4*>(&C[(size_t)row * N + col0]) = o0;
        *reinterpret_cast<float4*>(&C[(size_t)row * N + col0 + 4]) = o1;
    }
}

// ---------------- LSTM scan layers 0/1 (R3 bytes, FROZEN) ------------------
template<int INDIM, int OUTDIM, int LAYER>
__global__ void __launch_bounds__(256, 1)
lstm_scan(const float* __restrict__ whh,       // [4*OUTDIM][INDIM]
          const int*   __restrict__ tokens,    // layer 0 only
          float*       __restrict__ hs_param)  // unused here
{
    constexpr int KITER = INDIM / 128;
    constexpr int PPT   = INDIM / 256;

    const float* pre = (LAYER == 0) ? g_table : g_pre1;
    ull*   tg = (LAYER == 0) ? g_tg0 : g_tg1;
    float* hs = (LAYER == 0) ? g_hs0 : g_hs1;
    float* cf = g_cfin + ((LAYER == 0) ? 0 : HID);

    const int tid = threadIdx.x;
    const int w = tid >> 5;
    const int l = tid & 31;
    const int out = blockIdx.x * 8 + w;
    const unsigned tb = g_gen * (unsigned)(SEQ + 1);

    __shared__ __align__(16) float sh[2][INDIM];
    __shared__ int stok[(LAYER == 0) ? SEQ : 1];

    ulonglong2 wq[4][KITER];
#pragma unroll
    for (int r = 0; r < 4; r++)
#pragma unroll
        for (int i = 0; i < KITER; i++)
            wq[r][i] = *reinterpret_cast<const ulonglong2*>(
                whh + (size_t)(r * OUTDIM + out) * INDIM + i * 128 + 4 * l);

    if constexpr (LAYER == 0) {
        for (int i = tid; i < SEQ; i += 256) stok[i] = tokens[i];
    }
    for (int i = tid; i < INDIM; i += 256) sh[0][i] = 0.0f;
    __syncthreads();

    auto loadpre = [&](int tt, int r) -> float {
        if constexpr (LAYER == 0)
            return __ldg(&pre[(size_t)stok[tt] * (4 * OUTDIM) + r * OUTDIM + out]);
        else
            return __ldg(&pre[(size_t)tt * (4 * OUTDIM) + r * OUTDIM + out]);
    };

    float c = 0.0f;
    float pv = (l < 4) ? loadpre(0, l) : 0.0f;

    for (int t = 0; t < SEQ; t++) {
        float pvn = (l < 4 && t + 1 < SEQ) ? loadpre(t + 1, l) : 0.0f;

        float* shb = sh[t & 1];
        if (t > 0) {
            const ull* src = tg + (size_t)(t - 1) * INDIM;
            const unsigned expect = tb + (unsigned)t;
            ull v[PPT];
#pragma unroll
            for (int j = 0; j < PPT; j++) v[j] = ld_tag(src + tid + 256 * j);
            while (true) {
                bool ok = true;
#pragma unroll
                for (int j = 0; j < PPT; j++) ok &= ((unsigned)(v[j] >> 32) == expect);
                if (ok) break;
#pragma unroll
                for (int j = 0; j < PPT; j++) v[j] = ld_tag(src + tid + 256 * j);
            }
#pragma unroll
            for (int j = 0; j < PPT; j++)
                shb[tid + 256 * j] = __uint_as_float((unsigned)v[j]);
        }
        __syncthreads();

        ull acc[4] = {0ull, 0ull, 0ull, 0ull};
#pragma unroll
        for (int i = 0; i < KITER; i++) {
            ulonglong2 hv = *reinterpret_cast<const ulonglong2*>(shb + i * 128 + 4 * l);
#pragma unroll
            for (int r = 0; r < 4; r++) {
                acc[r] = fma2(wq[r][i].x, hv.x, acc[r]);
                acc[r] = fma2(wq[r][i].y, hv.y, acc[r]);
            }
        }
        float g[4];
#pragma unroll
        for (int r = 0; r < 4; r++) g[r] = lo32(acc[r]) + hi32(acc[r]);
#pragma unroll
        for (int s = 16; s > 0; s >>= 1)
#pragma unroll
            for (int r = 0; r < 4; r++) g[r] += __shfl_xor_sync(0xffffffffu, g[r], s);

        const float p0 = __shfl_sync(0xffffffffu, pv, 0);
        const float p1 = __shfl_sync(0xffffffffu, pv, 1);
        const float p2 = __shfl_sync(0xffffffffu, pv, 2);
        const float p3 = __shfl_sync(0xffffffffu, pv, 3);

        c = fsig(g[1] + p1) * c + fsig(g[0] + p0) * ftanh(g[2] + p2);
        const float h = fsig(g[3] + p3) * ftanh(c);

        if (l == 0) {
            st_tag(tg + (size_t)t * OUTDIM + out,
                   ((ull)(tb + (unsigned)t + 1u) << 32) | (ull)__float_as_uint(h));
            hs[(size_t)t * OUTDIM + out] = h;
            if (t == SEQ - 1) cf[out] = c;
        }
        pv = pvn;
    }
}

// ---------------- layer-2 scan (R16 bytes): 8-CTA cluster, DSMEM -----------
__global__ void __cluster_dims__(8, 1, 1) __launch_bounds__(256, 1)
lstm_scan2_cluster(const float* __restrict__ whh, float* __restrict__ outp)
{
    const int tid = threadIdx.x;
    const int w = tid >> 5;
    const int l = tid & 31;
    const int g = l >> 3;
    const int j = l & 7;
    uint32_t rank;
    asm("mov.u32 %0, %%cluster_ctarank;" : "=r"(rank));
    const int o = (int)rank * 32 + w * 4 + g;

    __shared__ __align__(16) float sh2[2][NCLS];
    const uint32_t sh2_base = smem_u32(&sh2[0][0]);

    ulonglong2 wq[4][8];
#pragma unroll
    for (int r = 0; r < 4; r++)
#pragma unroll
        for (int i = 0; i < 8; i++)
            wq[r][i] = *reinterpret_cast<const ulonglong2*>(
                whh + (size_t)(r * NCLS + o) * NCLS + 32 * i + 4 * j);

    for (int i = tid; i < NCLS; i += 256) sh2[0][i] = 0.0f;   // h2_{-1} = 0
    __syncthreads();

    float c = 0.0f;
    float pv[4];
#pragma unroll
    for (int r = 0; r < 4; r++)
        pv[r] = __ldg(&g_pre2[(size_t)0 * (4 * NCLS) + r * NCLS + o]);

    for (int t = 0; t < SEQ; t++) {
        float pvn[4] = {0.f, 0.f, 0.f, 0.f};
        if (t + 1 < SEQ) {
#pragma unroll
            for (int r = 0; r < 4; r++)
                pvn[r] = __ldg(&g_pre2[(size_t)(t + 1) * (4 * NCLS) + r * NCLS + o]);
        }

        const float* shb = sh2[t & 1];
        ull acc[4] = {0ull, 0ull, 0ull, 0ull};
#pragma unroll
        for (int i = 0; i < 8; i++) {
            ulonglong2 hv = *reinterpret_cast<const ulonglong2*>(shb + 32 * i + 4 * j);
#pragma unroll
            for (int r = 0; r < 4; r++) {
                acc[r] = fma2(wq[r][i].x, hv.x, acc[r]);
                acc[r] = fma2(wq[r][i].y, hv.y, acc[r]);
            }
        }
        ull p01 = pack2(lo32(acc[0]) + hi32(acc[0]), lo32(acc[1]) + hi32(acc[1]));
        ull p23 = pack2(lo32(acc[2]) + hi32(acc[2]), lo32(acc[3]) + hi32(acc[3]));
#pragma unroll
        for (int s = 4; s > 0; s >>= 1) {
            p01 = add2(p01, __shfl_xor_sync(0xffffffffu, p01, s));
            p23 = add2(p23, __shfl_xor_sync(0xffffffffu, p23, s));
        }
        const float s0 = lo32(p01) + pv[0];   // i  (pre2 already has biases)
        const float s1 = hi32(p01) + pv[1];   // f
        const float s2 = lo32(p23) + pv[2];   // g
        const float s3 = hi32(p23) + pv[3];   // o

        c = fsig(s1) * c + fsig(s0) * ftanh(s2);
        const float h = fsig(s3) * ftanh(c);

        if (j == 0) {
            outp[(size_t)t * NCLS + o] = h;
            if (t == SEQ - 1) g_cfin[2 * HID + o] = c;
            const uint32_t dst = sh2_base + (uint32_t)((((t + 1) & 1) * NCLS + o) * 4);
#pragma unroll
            for (uint32_t rk = 0; rk < 8; rk++) st_dsmem(dst, rk, h);
        }
        asm volatile("barrier.cluster.arrive.aligned;" ::: "memory");
        asm volatile("barrier.cluster.wait.aligned;" ::: "memory");

#pragma unroll
        for (int r = 0; r < 4; r++) pv[r] = pvn[r];
    }
}

// ---------------- final output assembly ----------------
__global__ void finalize_kernel(float* __restrict__ out) {
    int i = blockIdx.x * blockDim.x + threadIdx.x;
    const int OB = SEQ * NCLS;   // 1048576: start of h_stack
    if (i < 1024)      out[OB + i] = g_hs0[(SEQ - 1) * HID + i];
    else if (i < 2048) out[OB + i] = g_hs1[(SEQ - 1) * HID + (i - 1024)];
    else if (i < 3072) out[OB + i] = g_cfin[i - 2048];                   // c0
    else if (i < 4096) out[OB + i] = g_cfin[HID + (i - 3072)];           // c1
    else if (i < 4352) out[OB + i] = out[(SEQ - 1) * NCLS + (i - 4096)]; // h2
    else if (i < 4608) out[OB + i] = g_cfin[2 * HID + (i - 4352)];       // c2
}

// ---------------- launch ----------------
extern "C" void kernel_launch(void* const* d_in, const int* in_sizes, int n_in,
                              void* d_out, int out_size)
{
    const int*   tokens = (const int*)  d_in[0];
    const float* embed  = (const float*)d_in[1];
    const float* w_ih0  = (const float*)d_in[2];
    const float* w_hh0  = (const float*)d_in[3];
    const float* b_ih0  = (const float*)d_in[4];
    const float* b_hh0  = (const float*)d_in[5];
    const float* w_ih1  = (const float*)d_in[6];
    const float* w_hh1  = (const float*)d_in[7];
    const float* b_ih1  = (const float*)d_in[8];
    const float* b_hh1  = (const float*)d_in[9];
    const float* w_ih2  = (const float*)d_in[10];
    const float* w_hh2  = (const float*)d_in[11];
    const float* b_ih2  = (const float*)d_in[12];
    const float* b_hh2  = (const float*)d_in[13];
    float* out = (float*)d_out;

    bump_gen_kernel<<<1, 32>>>();

    // layer 0 pre-activation table: [256 classes][4096 gate rows]
    gemm_bias<0><<<dim3(4 * HID / 128, NCLS / 128), 256>>>(embed, w_ih0, b_ih0, b_hh0,
                                                           NCLS, 4 * HID, HID);
    lstm_scan<HID, HID, 0><<<HID / 8, 256>>>(w_hh0, tokens, nullptr);

    gemm_bias<1><<<dim3(4 * HID / 128, SEQ / 128), 256>>>(nullptr, w_ih1, b_ih1, b_hh1,
                                                          SEQ, 4 * HID, HID);
    lstm_scan<HID, HID, 1><<<HID / 8, 256>>>(w_hh1, nullptr, nullptr);

    gemm_bias<2><<<dim3(4 * NCLS / 128, SEQ / 128), 256>>>(nullptr, w_ih2, b_ih2, b_hh2,
                                                           SEQ, 4 * NCLS, HID);
    // layer 2: one 8-CTA cluster, DSMEM recurrence
    lstm_scan2_cluster<<<8, 256>>>(w_hh2, out);

    finalize_kernel<<<18, 256>>>(out);
}